// round 7
// baseline (speedup 1.0000x reference)
#include <cuda_runtime.h>

#define BB 2
#define NN 512
#define FF 64
#define H1 256
#define KT 16
#define QT 2
#define PP 32      // pairs per chunk = QT*KT
#define G1LD 36    // padded row length (floats) for g1T rows (144B: 16B-aligned)

// ---------------- scratch (static device allocs are allowed) ----------------
__device__ float g_Aq[BB * NN * H1];      // qs@Wa1[0:64] + ba1
__device__ float g_Ak[BB * NN * H1];      // ks@Wa1[64:128]
__device__ float g_vproj[BB * NN * FF];   // vs@Wv + bv
__device__ float g_gpart[BB * 16 * FF];   // pooled-max partials

// ---------------- helpers ----------------
__device__ __forceinline__ float gelu_t(float x) {
    // jax.nn.gelu approximate=True: 0.5x(1+tanh(sqrt(2/pi)(x+0.044715x^3)))
    float u = 0.7978845608028654f * x * fmaf(0.044715f, x * x, 1.0f);
    float e = exp2f(u * 2.885390081777927f);            // exp(2u)
    float t = 1.0f - __fdividef(2.0f, e + 1.0f);        // tanh(u)
    return 0.5f * x * (1.0f + t);
}

__device__ __forceinline__ float warp_sum(float v) {
    v += __shfl_xor_sync(0xffffffffu, v, 16);
    v += __shfl_xor_sync(0xffffffffu, v, 8);
    v += __shfl_xor_sync(0xffffffffu, v, 4);
    v += __shfl_xor_sync(0xffffffffu, v, 2);
    v += __shfl_xor_sync(0xffffffffu, v, 1);
    return v;
}

// ---------------- K1: precompute Aq, Ak, vproj ----------------
__global__ void k_pre(const float* __restrict__ qs, const float* __restrict__ ks,
                      const float* __restrict__ vs,
                      const float* __restrict__ Wa1, const float* __restrict__ ba1,
                      const float* __restrict__ Wv, const float* __restrict__ bv) {
    __shared__ float xs[4096];
    int t = threadIdx.x;
    int bid = blockIdx.x;

    if (bid < 128) {
        bool isQ = (bid < 64);
        int rb = (isQ ? bid : bid - 64) * 16;           // row base 0..1023
        const float* src = isQ ? qs : ks;
        #pragma unroll
        for (int u = 0; u < 4; u++) xs[t + 256 * u] = src[rb * FF + t + 256 * u];
        __syncthreads();
        const float* W = Wa1 + (isQ ? 0 : FF) * H1;
        float acc[16];
        float binit = isQ ? ba1[t] : 0.0f;
        #pragma unroll
        for (int r = 0; r < 16; r++) acc[r] = binit;
        for (int f = 0; f < FF; f++) {
            float w = W[f * H1 + t];
            #pragma unroll
            for (int r = 0; r < 16; r++) acc[r] = fmaf(xs[r * FF + f], w, acc[r]);
        }
        float* dst = (isQ ? g_Aq : g_Ak) + rb * H1 + t;
        #pragma unroll
        for (int r = 0; r < 16; r++) dst[r * H1] = acc[r];
    } else {
        int rb = (bid - 128) * 64;                      // 64 rows per block
        #pragma unroll
        for (int u = 0; u < 16; u++) xs[t + 256 * u] = vs[rb * FF + t + 256 * u];
        __syncthreads();
        int d = t & 63, rq = t >> 6;                    // rq handles rows rq*16..rq*16+15
        float acc[16];
        float binit = bv[d];
        #pragma unroll
        for (int r = 0; r < 16; r++) acc[r] = binit;
        for (int f = 0; f < FF; f++) {
            float w = Wv[f * FF + d];
            #pragma unroll
            for (int r = 0; r < 16; r++) acc[r] = fmaf(xs[(rq * 16 + r) * FF + f], w, acc[r]);
        }
        #pragma unroll
        for (int r = 0; r < 16; r++) g_vproj[(rb + rq * 16 + r) * FF + d] = acc[r];
    }
}

// ---------------- K2: fused pair-MLP attention + ctx + LN ----------------
// Reference mask semantics: mask[b,q,k] = (q < valid_lens[b]) && (t_diff[b,q,k] > 0).
// The einsum over k is UNMASKED in k: all 512 keys contribute for valid q.
// Rows with q >= vl have attn == 0 -> ctx row = LN(0) = ln1_b (early exit).
__global__ void __launch_bounds__(256) k_main(
    const float* __restrict__ qs_s, const float* __restrict__ ks_s,
    const float* __restrict__ qs_t, const float* __restrict__ ks_t,
    const int* __restrict__ valid_lens,
    const float* __restrict__ Wa1, const float* __restrict__ Wa2,
    const float* __restrict__ ba2, const float* __restrict__ Wa3,
    const float* __restrict__ ba3,
    const float* __restrict__ ln1_s, const float* __restrict__ ln1_b,
    float* __restrict__ out)
{
    __shared__ __align__(16) float g1T[H1 * G1LD];   // 36 KB, [i][p] padded rows
    __shared__ float ex[5][PP];
    __shared__ float attn_s[PP];
    __shared__ float red[8 * PP];
    __shared__ float lnred[16];

    int t = threadIdx.x;
    int lane = t & 31, wrp = t >> 5;
    int b = blockIdx.x & 1;
    int q0 = (blockIdx.x >> 1) * QT;
    int vl = valid_lens[b];

    // Whole block invalid (q0 >= vl): attn rows are all zero -> ctx = ln1_b.
    if (q0 >= vl) {
        if (t < 128) {
            int qt = t >> 6, d = t & 63;
            out[(b * NN + q0 + qt) * FF + d] = ln1_b[d];
        }
        return;
    }

    int j = t;  // hidden feature owned by this thread
    float aq0 = g_Aq[(b * NN + q0) * H1 + j];
    float aq1 = g_Aq[(b * NN + q0 + 1) * H1 + j];
    float w5[5];
    #pragma unroll
    for (int c = 0; c < 5; c++) w5[c] = Wa1[(2 * FF + c) * H1 + j];
    float ba2j = ba2[j];
    float wa3j = Wa3[j];
    float ba3v = ba3[0];

    float ctxacc = 0.0f;  // thread t<128 owns (qt=t>>6, d=t&63)

    for (int kc = 0; kc < NN / KT; kc++) {   // ALL 512 keys — k is not masked
        int kbase = kc * KT;

        // ---- extras for 32 pairs ----
        if (t < PP) {
            int qt = t >> 4, kk = t & 15;
            int q = q0 + qt, k = kbase + kk;
            float e0 = qs_s[(b * NN + q) * 2]     - ks_s[(b * NN + k) * 2];
            float e1 = qs_s[(b * NN + q) * 2 + 1] - ks_s[(b * NN + k) * 2 + 1];
            float d2 = e0 * e0 + e1 * e1;
            float e4 = qs_t[b * NN + q] - ks_t[b * NN + k];
            ex[0][t] = e0; ex[1][t] = e1; ex[2][t] = sqrtf(d2);
            ex[3][t] = d2; ex[4][t] = e4;
        }
        __syncthreads();

        // ---- g1 = gelu(layer1) into transposed smem [i=j][p] ----
        {
            float ak[KT];
            #pragma unroll
            for (int kk = 0; kk < KT; kk++)
                ak[kk] = g_Ak[(b * NN + kbase + kk) * H1 + j];
            #pragma unroll
            for (int p = 0; p < PP; p++) {
                int qt = p >> 4, kk = p & 15;
                float x = (qt ? aq1 : aq0) + ak[kk];
                x = fmaf(ex[0][p], w5[0], x);
                x = fmaf(ex[1][p], w5[1], x);
                x = fmaf(ex[2][p], w5[2], x);
                x = fmaf(ex[3][p], w5[3], x);
                x = fmaf(ex[4][p], w5[4], x);
                g1T[j * G1LD + p] = gelu_t(x);
            }
        }
        __syncthreads();

        // ---- layer2 GEMM: acc[p] = sum_i g1[p][i] * Wa2[i][j], FFMA2 packed ----
        unsigned long long acc[16];
        #pragma unroll
        for (int r = 0; r < 16; r++) acc[r] = 0ULL;
        float wc[8], wn[8];
        #pragma unroll
        for (int r = 0; r < 8; r++) wc[r] = Wa2[r * H1 + j];
        #pragma unroll 1
        for (int ib = 0; ib < 32; ib++) {
            if (ib < 31) {
                #pragma unroll
                for (int r = 0; r < 8; r++) wn[r] = Wa2[((ib + 1) * 8 + r) * H1 + j];
            }
            #pragma unroll
            for (int r = 0; r < 8; r++) {
                int i = ib * 8 + r;
                unsigned long long wd;
                asm("mov.b64 %0, {%1, %2};" : "=l"(wd) : "f"(wc[r]), "f"(wc[r]));
                const ulonglong2* row = reinterpret_cast<const ulonglong2*>(&g1T[i * G1LD]);
                #pragma unroll
                for (int pp = 0; pp < 8; pp++) {
                    ulonglong2 g = row[pp];
                    asm("fma.rn.f32x2 %0, %1, %2, %0;" : "+l"(acc[pp * 2])     : "l"(g.x), "l"(wd));
                    asm("fma.rn.f32x2 %0, %1, %2, %0;" : "+l"(acc[pp * 2 + 1]) : "l"(g.y), "l"(wd));
                }
            }
            #pragma unroll
            for (int r = 0; r < 8; r++) wc[r] = wn[r];
        }

        // ---- epilogue: bias, gelu, *Wa3, reduce over j ----
        float sel = 0.0f;
        #pragma unroll
        for (int pr = 0; pr < 16; pr++) {
            float lo, hi;
            asm("mov.b64 {%0, %1}, %2;" : "=f"(lo), "=f"(hi) : "l"(acc[pr]));
            float c0 = gelu_t(lo + ba2j) * wa3j;
            float c1 = gelu_t(hi + ba2j) * wa3j;
            c0 = warp_sum(c0);
            c1 = warp_sum(c1);
            if (lane == 2 * pr)     sel = c0;
            if (lane == 2 * pr + 1) sel = c1;
        }
        red[wrp * PP + lane] = sel;
        __syncthreads();

        if (t < PP) {
            float s = ba3v;
            #pragma unroll
            for (int w = 0; w < 8; w++) s += red[w * PP + t];
            int qt = t >> 4;
            // mask is on the QUERY axis: (q < vl) && (t_diff > 0)
            bool ok = ((q0 + qt) < vl) && (ex[4][t] > 0.0f);
            attn_s[t] = ok ? s : 0.0f;
        }
        __syncthreads();

        // ---- ctx accumulation (over all k) ----
        if (t < 128) {
            int qt = t >> 6, d = t & 63;
            #pragma unroll
            for (int kk = 0; kk < KT; kk++)
                ctxacc = fmaf(attn_s[qt * KT + kk],
                              g_vproj[(b * NN + kbase + kk) * FF + d], ctxacc);
        }
        __syncthreads();
    }

    // ---- LayerNorm over d=64 per q-row (two-pass) ----
    float x = ctxacc;
    float s = warp_sum(x);
    if (lane == 0) lnred[wrp] = s;
    __syncthreads();
    int g2 = (t >> 6) & 3;                 // q-row group: warps {0,1} -> row 0, {2,3} -> row 1
    float mu = (lnred[g2 * 2] + lnred[g2 * 2 + 1]) * (1.0f / 64.0f);
    float y = x - mu;
    float s2 = warp_sum(y * y);
    if (lane == 0) lnred[8 + wrp] = s2;
    __syncthreads();
    float var = (lnred[8 + g2 * 2] + lnred[8 + g2 * 2 + 1]) * (1.0f / 64.0f);
    if (t < 128) {
        int qt = t >> 6, d = t & 63;
        float o = y * rsqrtf(var + 1e-6f) * ln1_s[d] + ln1_b[d];
        out[(b * NN + q0 + qt) * FF + d] = o;
    }
}

// ---------------- K3: gate MLP + masked max-pool partials ----------------
__global__ void k_gate(const float* __restrict__ ctx, const int* __restrict__ valid_lens,
                       const float* __restrict__ Wg1, const float* __restrict__ bg1,
                       const float* __restrict__ Wg2, const float* __restrict__ bg2)
{
    __shared__ float ctx_s[32 * FF];
    __shared__ float hs[H1];
    __shared__ float gsum[4 * FF];
    int t = threadIdx.x;
    int b = blockIdx.x >> 4;
    int qg = blockIdx.x & 15;
    int qbase = qg * 32;
    int vl = valid_lens[b];
    #pragma unroll
    for (int u = 0; u < 8; u++)
        ctx_s[t + 256 * u] = ctx[(b * NN + qbase) * FF + t + 256 * u];
    __syncthreads();

    float lmax = -3.4e38f;
    for (int q = 0; q < 32; q++) {
        float a = bg1[t];
        #pragma unroll 8
        for (int f = 0; f < FF; f++) a = fmaf(ctx_s[q * FF + f], Wg1[f * H1 + t], a);
        hs[t] = gelu_t(a);
        __syncthreads();
        int d = t & 63, part = t >> 6;
        float s = 0.0f;
        #pragma unroll 8
        for (int jj = 0; jj < 64; jj++)
            s = fmaf(hs[part * 64 + jj], Wg2[(part * 64 + jj) * FF + d], s);
        gsum[part * FF + d] = s;
        __syncthreads();
        if (t < FF) {
            float g = bg2[t] + gsum[t] + gsum[FF + t] + gsum[2 * FF + t] + gsum[3 * FF + t];
            float gp = g * ctx_s[q * FF + t];
            float m = ((qbase + q) < vl) ? gp : -3.4e38f;
            lmax = fmaxf(lmax, m);
        }
        __syncthreads();
    }
    if (t < FF) g_gpart[(b * 16 + qg) * FF + t] = lmax;
}

// ---------------- K4: final max + LN -> vnode ----------------
__global__ void k_vnode(float* __restrict__ out,
                        const float* __restrict__ ln2_s, const float* __restrict__ ln2_b) {
    __shared__ float r4[4];
    int b = blockIdx.x, d = threadIdx.x;  // 64 threads
    float m = -3.4e38f;
    #pragma unroll
    for (int g = 0; g < 16; g++) m = fmaxf(m, g_gpart[(b * 16 + g) * FF + d]);
    float s = warp_sum(m);
    if ((d & 31) == 0) r4[d >> 5] = s;
    __syncthreads();
    float mu = (r4[0] + r4[1]) * (1.0f / 64.0f);
    float y = m - mu;
    float s2 = warp_sum(y * y);
    if ((d & 31) == 0) r4[2 + (d >> 5)] = s2;
    __syncthreads();
    float var = (r4[2] + r4[3]) * (1.0f / 64.0f);
    out[BB * NN * FF + b * FF + d] = y * rsqrtf(var + 1e-6f) * ln2_s[d] + ln2_b[d];
}

// ---------------- launch ----------------
extern "C" void kernel_launch(void* const* d_in, const int* in_sizes, int n_in,
                              void* d_out, int out_size) {
    (void)in_sizes; (void)n_in; (void)out_size;
    const float* qs    = (const float*)d_in[0];
    const float* ks    = (const float*)d_in[1];
    const float* vs    = (const float*)d_in[2];
    const float* qs_s  = (const float*)d_in[3];
    const float* ks_s  = (const float*)d_in[4];
    const float* qs_t  = (const float*)d_in[5];
    const float* ks_t  = (const float*)d_in[6];
    const int*   vlen  = (const int*)  d_in[7];
    const float* Wv    = (const float*)d_in[8];
    const float* bv    = (const float*)d_in[9];
    const float* Wa1   = (const float*)d_in[10];
    const float* ba1   = (const float*)d_in[11];
    const float* Wa2   = (const float*)d_in[12];
    const float* ba2   = (const float*)d_in[13];
    const float* Wa3   = (const float*)d_in[14];
    const float* ba3   = (const float*)d_in[15];
    const float* Wg1   = (const float*)d_in[16];
    const float* bg1   = (const float*)d_in[17];
    const float* Wg2   = (const float*)d_in[18];
    const float* bg2   = (const float*)d_in[19];
    const float* ln1_s = (const float*)d_in[20];
    const float* ln1_b = (const float*)d_in[21];
    const float* ln2_s = (const float*)d_in[22];
    const float* ln2_b = (const float*)d_in[23];
    float* out = (float*)d_out;

    k_pre  <<<144, 256>>>(qs, ks, vs, Wa1, ba1, Wv, bv);
    k_main <<<BB * (NN / QT), 256>>>(qs_s, ks_s, qs_t, ks_t, vlen,
                                     Wa1, Wa2, ba2, Wa3, ba3, ln1_s, ln1_b, out);
    k_gate <<<32, 256>>>(out, vlen, Wg1, bg1, Wg2, bg2);
    k_vnode<<<BB, 64>>>(out, ln2_s, ln2_b);
}

// round 12
// speedup vs baseline: 1.4319x; 1.4319x over previous
#include <cuda_runtime.h>

#define BB 2
#define NN 512
#define FF 64
#define H1 256
#define QT 2
#define KB 64          // keys per tile
#define P  128         // pairs per tile = QT*KB
#define PL 132         // g1T row pitch in floats (16B-aligned, conflict-free)
#define NTILE (NN / KB)

// smem layout (floats): g1T[256*PL] | ex4[128*4] | ext[128] | attn[128] | lnred[16]
#define SM_G1    0
#define SM_EX4   (H1 * PL)
#define SM_EXT   (SM_EX4 + P * 4)
#define SM_ATTN  (SM_EXT + P)
#define SM_LNRED (SM_ATTN + P)
#define SM_FLOATS (SM_LNRED + 16)

// ---------------- scratch ----------------
__device__ float g_Aq[BB * NN * H1];      // qs@Wa1[0:64] + ba1
__device__ float g_Ak[BB * NN * H1];      // ks@Wa1[64:128]
__device__ float g_vproj[BB * NN * FF];   // vs@Wv + bv
__device__ float g_gpart[BB * 16 * FF];   // pooled-max partials

// ---------------- helpers ----------------
__device__ __forceinline__ float gelu_t(float x) {
    float u = 0.7978845608028654f * x * fmaf(0.044715f, x * x, 1.0f);
    float e = exp2f(u * 2.885390081777927f);            // exp(2u)
    float t = 1.0f - __fdividef(2.0f, e + 1.0f);        // tanh(u)
    return 0.5f * x * (1.0f + t);
}

__device__ __forceinline__ float warp_sum(float v) {
    v += __shfl_xor_sync(0xffffffffu, v, 16);
    v += __shfl_xor_sync(0xffffffffu, v, 8);
    v += __shfl_xor_sync(0xffffffffu, v, 4);
    v += __shfl_xor_sync(0xffffffffu, v, 2);
    v += __shfl_xor_sync(0xffffffffu, v, 1);
    return v;
}

// ---------------- K1: precompute Aq, Ak, vproj ----------------
__global__ void k_pre(const float* __restrict__ qs, const float* __restrict__ ks,
                      const float* __restrict__ vs,
                      const float* __restrict__ Wa1, const float* __restrict__ ba1,
                      const float* __restrict__ Wv, const float* __restrict__ bv) {
    __shared__ float xs[4096];
    int t = threadIdx.x;
    int bid = blockIdx.x;

    if (bid < 128) {
        bool isQ = (bid < 64);
        int rb = (isQ ? bid : bid - 64) * 16;
        const float* src = isQ ? qs : ks;
        #pragma unroll
        for (int u = 0; u < 4; u++) xs[t + 256 * u] = src[rb * FF + t + 256 * u];
        __syncthreads();
        const float* W = Wa1 + (isQ ? 0 : FF) * H1;
        float acc[16];
        float binit = isQ ? ba1[t] : 0.0f;
        #pragma unroll
        for (int r = 0; r < 16; r++) acc[r] = binit;
        for (int f = 0; f < FF; f++) {
            float w = W[f * H1 + t];
            #pragma unroll
            for (int r = 0; r < 16; r++) acc[r] = fmaf(xs[r * FF + f], w, acc[r]);
        }
        float* dst = (isQ ? g_Aq : g_Ak) + rb * H1 + t;
        #pragma unroll
        for (int r = 0; r < 16; r++) dst[r * H1] = acc[r];
    } else {
        int rb = (bid - 128) * 64;
        #pragma unroll
        for (int u = 0; u < 16; u++) xs[t + 256 * u] = vs[rb * FF + t + 256 * u];
        __syncthreads();
        int d = t & 63, rq = t >> 6;
        float acc[16];
        float binit = bv[d];
        #pragma unroll
        for (int r = 0; r < 16; r++) acc[r] = binit;
        for (int f = 0; f < FF; f++) {
            float w = Wv[f * FF + d];
            #pragma unroll
            for (int r = 0; r < 16; r++) acc[r] = fmaf(xs[(rq * 16 + r) * FF + f], w, acc[r]);
        }
        #pragma unroll
        for (int r = 0; r < 16; r++) g_vproj[(rb + rq * 16 + r) * FF + d] = acc[r];
    }
}

// ---------------- K2: fused pair-MLP attention + ctx + LN ----------------
// mask[b,q,k] = (q < vl[b]) && (t_diff > 0); einsum over k is unmasked in k.
__global__ void __launch_bounds__(256, 1) k_main(
    const float* __restrict__ qs_s, const float* __restrict__ ks_s,
    const float* __restrict__ qs_t, const float* __restrict__ ks_t,
    const int* __restrict__ valid_lens,
    const float* __restrict__ Wa1, const float* __restrict__ Wa2,
    const float* __restrict__ ba2, const float* __restrict__ Wa3,
    const float* __restrict__ ba3,
    const float* __restrict__ ln1_s, const float* __restrict__ ln1_b,
    float* __restrict__ out)
{
    extern __shared__ float sm[];
    float* g1T    = sm + SM_G1;
    float4* ex4s  = reinterpret_cast<float4*>(sm + SM_EX4);
    float* exts   = sm + SM_EXT;
    float* attn_s = sm + SM_ATTN;
    float* lnred  = sm + SM_LNRED;

    int t = threadIdx.x;
    int lane = t & 31, wrp = t >> 5;
    int b = blockIdx.x & 1;
    int q0 = (blockIdx.x >> 1) * QT;
    int vl = valid_lens[b];

    if (q0 >= vl) {  // whole block invalid: ctx rows = LN(0) = ln1_b
        if (t < 128) {
            int qt = t >> 6, d = t & 63;
            out[(b * NN + q0 + qt) * FF + d] = ln1_b[d];
        }
        return;
    }

    int j = t;
    float aq0 = g_Aq[(b * NN + q0) * H1 + j];
    float aq1 = g_Aq[(b * NN + q0 + 1) * H1 + j];
    float w5[5];
    #pragma unroll
    for (int c = 0; c < 5; c++) w5[c] = Wa1[(2 * FF + c) * H1 + j];
    float ba3v = ba3[0];

    int jq = t & 15;       // j-quad within sub-sweep
    int pg = t >> 4;       // pair-octet group (0..15)
    const float4* W4  = reinterpret_cast<const float4*>(Wa2);   // rows of 64 float4
    const float4* B24 = reinterpret_cast<const float4*>(ba2);
    const float4* W34 = reinterpret_cast<const float4*>(Wa3);
    const float* g1p = g1T + pg * 8;

    float ctxacc = 0.0f;   // t<128 owns (qt=t>>6, d=t&63)

    for (int tile = 0; tile < NTILE; tile++) {
        int kbase = tile * KB;

        // ---- extras for 128 pairs ----
        if (t < P) {
            int qt = t >> 6, kk = t & 63;
            int q = q0 + qt, k = kbase + kk;
            float e0 = qs_s[(b * NN + q) * 2]     - ks_s[(b * NN + k) * 2];
            float e1 = qs_s[(b * NN + q) * 2 + 1] - ks_s[(b * NN + k) * 2 + 1];
            float d2 = e0 * e0 + e1 * e1;
            float e4 = qs_t[b * NN + q] - ks_t[b * NN + k];
            ex4s[t] = make_float4(e0, e1, sqrtf(d2), d2);
            exts[t] = e4;
        }
        __syncthreads();

        // ---- phase A: g1 = gelu(layer1), transposed [i=j][p], STS.128 ----
        #pragma unroll 4
        for (int kk4 = 0; kk4 < 16; kk4++) {
            float a[4];
            #pragma unroll
            for (int r = 0; r < 4; r++)
                a[r] = g_Ak[(b * NN + kbase + kk4 * 4 + r) * H1 + j];
            #pragma unroll
            for (int qt = 0; qt < 2; qt++) {
                float aqv = qt ? aq1 : aq0;
                float4 o;
                float vv[4];
                #pragma unroll
                for (int r = 0; r < 4; r++) {
                    int p = qt * KB + kk4 * 4 + r;
                    float4 e = ex4s[p];
                    float et = exts[p];
                    float x = aqv + a[r];
                    x = fmaf(e.x, w5[0], x);
                    x = fmaf(e.y, w5[1], x);
                    x = fmaf(e.z, w5[2], x);
                    x = fmaf(e.w, w5[3], x);
                    x = fmaf(et,  w5[4], x);
                    vv[r] = gelu_t(x);
                }
                o.x = vv[0]; o.y = vv[1]; o.z = vv[2]; o.w = vv[3];
                *reinterpret_cast<float4*>(&g1T[j * PL + qt * KB + kk4 * 4]) = o;
            }
        }
        __syncthreads();

        // ---- GEMM: 4 j-sub-sweeps, each thread = 8 pairs x 4 j ----
        float part[8];
        #pragma unroll
        for (int r = 0; r < 8; r++) part[r] = 0.0f;

        #pragma unroll 1
        for (int s = 0; s < 4; s++) {
            int wbase = s * 16 + jq;
            float4 ba2v = B24[wbase];
            float4 wa3v = W34[wbase];

            unsigned long long acc[16];
            #pragma unroll
            for (int r = 0; r < 16; r++) acc[r] = 0ULL;

            float4 wbuf[4];
            #pragma unroll
            for (int r = 0; r < 4; r++) wbuf[r] = W4[r * 64 + wbase];

            #pragma unroll 1
            for (int ib = 0; ib < 64; ib++) {
                #pragma unroll
                for (int u = 0; u < 4; u++) {
                    int i = ib * 4 + u;
                    float4 wcur = wbuf[u];
                    if (ib < 63) wbuf[u] = W4[(i + 4) * 64 + wbase];
                    ulonglong2 ga = *reinterpret_cast<const ulonglong2*>(g1p + i * PL);
                    ulonglong2 gb = *reinterpret_cast<const ulonglong2*>(g1p + i * PL + 4);
                    unsigned long long wd0, wd1, wd2, wd3;
                    asm("mov.b64 %0, {%1, %1};" : "=l"(wd0) : "f"(wcur.x));
                    asm("mov.b64 %0, {%1, %1};" : "=l"(wd1) : "f"(wcur.y));
                    asm("mov.b64 %0, {%1, %1};" : "=l"(wd2) : "f"(wcur.z));
                    asm("mov.b64 %0, {%1, %1};" : "=l"(wd3) : "f"(wcur.w));
                    asm("fma.rn.f32x2 %0, %1, %2, %0;" : "+l"(acc[0])  : "l"(ga.x), "l"(wd0));
                    asm("fma.rn.f32x2 %0, %1, %2, %0;" : "+l"(acc[1])  : "l"(ga.y), "l"(wd0));
                    asm("fma.rn.f32x2 %0, %1, %2, %0;" : "+l"(acc[2])  : "l"(gb.x), "l"(wd0));
                    asm("fma.rn.f32x2 %0, %1, %2, %0;" : "+l"(acc[3])  : "l"(gb.y), "l"(wd0));
                    asm("fma.rn.f32x2 %0, %1, %2, %0;" : "+l"(acc[4])  : "l"(ga.x), "l"(wd1));
                    asm("fma.rn.f32x2 %0, %1, %2, %0;" : "+l"(acc[5])  : "l"(ga.y), "l"(wd1));
                    asm("fma.rn.f32x2 %0, %1, %2, %0;" : "+l"(acc[6])  : "l"(gb.x), "l"(wd1));
                    asm("fma.rn.f32x2 %0, %1, %2, %0;" : "+l"(acc[7])  : "l"(gb.y), "l"(wd1));
                    asm("fma.rn.f32x2 %0, %1, %2, %0;" : "+l"(acc[8])  : "l"(ga.x), "l"(wd2));
                    asm("fma.rn.f32x2 %0, %1, %2, %0;" : "+l"(acc[9])  : "l"(ga.y), "l"(wd2));
                    asm("fma.rn.f32x2 %0, %1, %2, %0;" : "+l"(acc[10]) : "l"(gb.x), "l"(wd2));
                    asm("fma.rn.f32x2 %0, %1, %2, %0;" : "+l"(acc[11]) : "l"(gb.y), "l"(wd2));
                    asm("fma.rn.f32x2 %0, %1, %2, %0;" : "+l"(acc[12]) : "l"(ga.x), "l"(wd3));
                    asm("fma.rn.f32x2 %0, %1, %2, %0;" : "+l"(acc[13]) : "l"(ga.y), "l"(wd3));
                    asm("fma.rn.f32x2 %0, %1, %2, %0;" : "+l"(acc[14]) : "l"(gb.x), "l"(wd3));
                    asm("fma.rn.f32x2 %0, %1, %2, %0;" : "+l"(acc[15]) : "l"(gb.y), "l"(wd3));
                }
            }

            // epilogue: bias, gelu, *Wa3, accumulate per-pair partials
            float bj[4] = {ba2v.x, ba2v.y, ba2v.z, ba2v.w};
            float wj[4] = {wa3v.x, wa3v.y, wa3v.z, wa3v.w};
            #pragma unroll
            for (int jj = 0; jj < 4; jj++) {
                #pragma unroll
                for (int pp2 = 0; pp2 < 4; pp2++) {
                    float lo, hi;
                    asm("mov.b64 {%0, %1}, %2;" : "=f"(lo), "=f"(hi) : "l"(acc[jj * 4 + pp2]));
                    part[pp2 * 2]     += gelu_t(lo + bj[jj]) * wj[jj];
                    part[pp2 * 2 + 1] += gelu_t(hi + bj[jj]) * wj[jj];
                }
            }
        }

        // ---- reduce over jq (16 lanes), mask, write attn ----
        #pragma unroll
        for (int r = 0; r < 8; r++) {
            float v = part[r];
            v += __shfl_xor_sync(0xffffffffu, v, 1);
            v += __shfl_xor_sync(0xffffffffu, v, 2);
            v += __shfl_xor_sync(0xffffffffu, v, 4);
            v += __shfl_xor_sync(0xffffffffu, v, 8);
            part[r] = v;
        }
        if (jq == 0) {
            #pragma unroll
            for (int r = 0; r < 8; r++) {
                int p = pg * 8 + r;
                int qt = p >> 6;
                bool ok = ((q0 + qt) < vl) && (exts[p] > 0.0f);
                attn_s[p] = ok ? (ba3v + part[r]) : 0.0f;
            }
        }
        __syncthreads();

        // ---- ctx accumulation ----
        if (t < 128) {
            int qt = t >> 6, d = t & 63;
            const float* vp = g_vproj + (b * NN + kbase) * FF + d;
            #pragma unroll 8
            for (int kk = 0; kk < KB; kk++)
                ctxacc = fmaf(attn_s[qt * KB + kk], vp[kk * FF], ctxacc);
        }
        __syncthreads();
    }

    // ---- LayerNorm over d=64 per q-row ----
    float x = ctxacc;
    float s = warp_sum(x);
    if (lane == 0) lnred[wrp] = s;
    __syncthreads();
    int g2 = (t >> 6) & 3;
    float mu = (lnred[g2 * 2] + lnred[g2 * 2 + 1]) * (1.0f / 64.0f);
    float y = x - mu;
    float s2 = warp_sum(y * y);
    if (lane == 0) lnred[8 + wrp] = s2;
    __syncthreads();
    float var = (lnred[8 + g2 * 2] + lnred[8 + g2 * 2 + 1]) * (1.0f / 64.0f);
    if (t < 128) {
        int qt = t >> 6, d = t & 63;
        float o = y * rsqrtf(var + 1e-6f) * ln1_s[d] + ln1_b[d];
        out[(b * NN + q0 + qt) * FF + d] = o;
    }
}

// ---------------- K3: gate MLP + masked max-pool partials ----------------
__global__ void k_gate(const float* __restrict__ ctx, const int* __restrict__ valid_lens,
                       const float* __restrict__ Wg1, const float* __restrict__ bg1,
                       const float* __restrict__ Wg2, const float* __restrict__ bg2)
{
    __shared__ float ctx_s[32 * FF];
    __shared__ float hs[H1];
    __shared__ float gsum[4 * FF];
    int t = threadIdx.x;
    int b = blockIdx.x >> 4;
    int qg = blockIdx.x & 15;
    int qbase = qg * 32;
    int vl = valid_lens[b];
    #pragma unroll
    for (int u = 0; u < 8; u++)
        ctx_s[t + 256 * u] = ctx[(b * NN + qbase) * FF + t + 256 * u];
    __syncthreads();

    float lmax = -3.4e38f;
    for (int q = 0; q < 32; q++) {
        float a = bg1[t];
        #pragma unroll 8
        for (int f = 0; f < FF; f++) a = fmaf(ctx_s[q * FF + f], Wg1[f * H1 + t], a);
        hs[t] = gelu_t(a);
        __syncthreads();
        int d = t & 63, part = t >> 6;
        float s = 0.0f;
        #pragma unroll 8
        for (int jj = 0; jj < 64; jj++)
            s = fmaf(hs[part * 64 + jj], Wg2[(part * 64 + jj) * FF + d], s);
        gsum[part * FF + d] = s;
        __syncthreads();
        if (t < FF) {
            float g = bg2[t] + gsum[t] + gsum[FF + t] + gsum[2 * FF + t] + gsum[3 * FF + t];
            float gp = g * ctx_s[q * FF + t];
            float m = ((qbase + q) < vl) ? gp : -3.4e38f;
            lmax = fmaxf(lmax, m);
        }
        __syncthreads();
    }
    if (t < FF) g_gpart[(b * 16 + qg) * FF + t] = lmax;
}

// ---------------- K4: final max + LN -> vnode ----------------
__global__ void k_vnode(float* __restrict__ out,
                        const float* __restrict__ ln2_s, const float* __restrict__ ln2_b) {
    __shared__ float r4[4];
    int b = blockIdx.x, d = threadIdx.x;
    float m = -3.4e38f;
    #pragma unroll
    for (int g = 0; g < 16; g++) m = fmaxf(m, g_gpart[(b * 16 + g) * FF + d]);
    float s = warp_sum(m);
    if ((d & 31) == 0) r4[d >> 5] = s;
    __syncthreads();
    float mu = (r4[0] + r4[1]) * (1.0f / 64.0f);
    float y = m - mu;
    float s2 = warp_sum(y * y);
    if ((d & 31) == 0) r4[2 + (d >> 5)] = s2;
    __syncthreads();
    float var = (r4[2] + r4[3]) * (1.0f / 64.0f);
    out[BB * NN * FF + b * FF + d] = y * rsqrtf(var + 1e-6f) * ln2_s[d] + ln2_b[d];
}

// ---------------- launch ----------------
extern "C" void kernel_launch(void* const* d_in, const int* in_sizes, int n_in,
                              void* d_out, int out_size) {
    (void)in_sizes; (void)n_in; (void)out_size;
    const float* qs    = (const float*)d_in[0];
    const float* ks    = (const float*)d_in[1];
    const float* vs    = (const float*)d_in[2];
    const float* qs_s  = (const float*)d_in[3];
    const float* ks_s  = (const float*)d_in[4];
    const float* qs_t  = (const float*)d_in[5];
    const float* ks_t  = (const float*)d_in[6];
    const int*   vlen  = (const int*)  d_in[7];
    const float* Wv    = (const float*)d_in[8];
    const float* bv    = (const float*)d_in[9];
    const float* Wa1   = (const float*)d_in[10];
    const float* ba1   = (const float*)d_in[11];
    const float* Wa2   = (const float*)d_in[12];
    const float* ba2   = (const float*)d_in[13];
    const float* Wa3   = (const float*)d_in[14];
    const float* ba3   = (const float*)d_in[15];
    const float* Wg1   = (const float*)d_in[16];
    const float* bg1   = (const float*)d_in[17];
    const float* Wg2   = (const float*)d_in[18];
    const float* bg2   = (const float*)d_in[19];
    const float* ln1_s = (const float*)d_in[20];
    const float* ln1_b = (const float*)d_in[21];
    const float* ln2_s = (const float*)d_in[22];
    const float* ln2_b = (const float*)d_in[23];
    float* out = (float*)d_out;

    static int smem_set = 0;
    const int smem_bytes = SM_FLOATS * 4;   // ~138.3 KB
    if (!smem_set) {
        cudaFuncSetAttribute(k_main, cudaFuncAttributeMaxDynamicSharedMemorySize, smem_bytes);
        smem_set = 1;
    }

    k_pre  <<<144, 256>>>(qs, ks, vs, Wa1, ba1, Wv, bv);
    k_main <<<BB * (NN / QT), 256, smem_bytes>>>(qs_s, ks_s, qs_t, ks_t, vlen,
                                                 Wa1, Wa2, ba2, Wa3, ba3, ln1_s, ln1_b, out);
    k_gate <<<32, 256>>>(out, vlen, Wg1, bg1, Wg2, bg2);
    k_vnode<<<BB, 64>>>(out, ln2_s, ln2_b);
}

// round 14
// speedup vs baseline: 1.4324x; 1.0003x over previous
#include <cuda_runtime.h>

#define BB 2
#define NN 512
#define FF 64
#define H1 256
#define QT 2
#define KB 64          // keys per tile
#define P  128         // pairs per tile = QT*KB
#define PL 132         // g1T row pitch in floats (16B-aligned, conflict-free)
#define NTILE (NN / KB)

// smem layout (floats): g1T[256*PL] | ex4[128*4] | ext[128] | attn[128] | lnred[16]
#define SM_G1    0
#define SM_EX4   (H1 * PL)
#define SM_EXT   (SM_EX4 + P * 4)
#define SM_ATTN  (SM_EXT + P)
#define SM_LNRED (SM_ATTN + P)
#define SM_FLOATS (SM_LNRED + 16)

// ---------------- scratch ----------------
__device__ float g_Aq[BB * NN * H1];      // qs@Wa1[0:64] + ba1
__device__ float g_Ak[BB * NN * H1];      // ks@Wa1[64:128]
__device__ float g_vproj[BB * NN * FF];   // vs@Wv + bv
__device__ float g_gpart[BB * 16 * FF];   // pooled-max partials

// ---------------- helpers ----------------
__device__ __forceinline__ float gelu_t(float x) {
    float u = 0.7978845608028654f * x * fmaf(0.044715f, x * x, 1.0f);
    float e = exp2f(u * 2.885390081777927f);            // exp(2u)
    float t = 1.0f - __fdividef(2.0f, e + 1.0f);        // tanh(u)
    return 0.5f * x * (1.0f + t);
}

__device__ __forceinline__ float warp_sum(float v) {
    v += __shfl_xor_sync(0xffffffffu, v, 16);
    v += __shfl_xor_sync(0xffffffffu, v, 8);
    v += __shfl_xor_sync(0xffffffffu, v, 4);
    v += __shfl_xor_sync(0xffffffffu, v, 2);
    v += __shfl_xor_sync(0xffffffffu, v, 1);
    return v;
}

// ---------------- K1: precompute Aq, Ak, vproj ----------------
__global__ void k_pre(const float* __restrict__ qs, const float* __restrict__ ks,
                      const float* __restrict__ vs,
                      const float* __restrict__ Wa1, const float* __restrict__ ba1,
                      const float* __restrict__ Wv, const float* __restrict__ bv) {
    __shared__ float xs[4096];
    int t = threadIdx.x;
    int bid = blockIdx.x;

    if (bid < 128) {
        bool isQ = (bid < 64);
        int rb = (isQ ? bid : bid - 64) * 16;
        const float* src = isQ ? qs : ks;
        #pragma unroll
        for (int u = 0; u < 4; u++) xs[t + 256 * u] = src[rb * FF + t + 256 * u];
        __syncthreads();
        const float* W = Wa1 + (isQ ? 0 : FF) * H1;
        float acc[16];
        float binit = isQ ? ba1[t] : 0.0f;
        #pragma unroll
        for (int r = 0; r < 16; r++) acc[r] = binit;
        for (int f = 0; f < FF; f++) {
            float w = W[f * H1 + t];
            #pragma unroll
            for (int r = 0; r < 16; r++) acc[r] = fmaf(xs[r * FF + f], w, acc[r]);
        }
        float* dst = (isQ ? g_Aq : g_Ak) + rb * H1 + t;
        #pragma unroll
        for (int r = 0; r < 16; r++) dst[r * H1] = acc[r];
    } else {
        int rb = (bid - 128) * 64;
        #pragma unroll
        for (int u = 0; u < 16; u++) xs[t + 256 * u] = vs[rb * FF + t + 256 * u];
        __syncthreads();
        int d = t & 63, rq = t >> 6;
        float acc[16];
        float binit = bv[d];
        #pragma unroll
        for (int r = 0; r < 16; r++) acc[r] = binit;
        for (int f = 0; f < FF; f++) {
            float w = Wv[f * FF + d];
            #pragma unroll
            for (int r = 0; r < 16; r++) acc[r] = fmaf(xs[(rq * 16 + r) * FF + f], w, acc[r]);
        }
        #pragma unroll
        for (int r = 0; r < 16; r++) g_vproj[(rb + rq * 16 + r) * FF + d] = acc[r];
    }
}

// ---------------- K2: fused pair-MLP attention + ctx + LN ----------------
// mask[b,q,k] = (q < vl[b]) && (t_diff > 0); einsum over k is unmasked in k.
__global__ void __launch_bounds__(256, 1) k_main(
    const float* __restrict__ qs_s, const float* __restrict__ ks_s,
    const float* __restrict__ qs_t, const float* __restrict__ ks_t,
    const int* __restrict__ valid_lens,
    const float* __restrict__ Wa1, const float* __restrict__ Wa2,
    const float* __restrict__ ba2, const float* __restrict__ Wa3,
    const float* __restrict__ ba3,
    const float* __restrict__ ln1_s, const float* __restrict__ ln1_b,
    float* __restrict__ out)
{
    extern __shared__ float sm[];
    float* g1T    = sm + SM_G1;
    float4* ex4s  = reinterpret_cast<float4*>(sm + SM_EX4);
    float* exts   = sm + SM_EXT;
    float* attn_s = sm + SM_ATTN;
    float* lnred  = sm + SM_LNRED;

    int t = threadIdx.x;
    int lane = t & 31, wrp = t >> 5;
    int b = blockIdx.x & 1;
    int q0 = (blockIdx.x >> 1) * QT;
    int vl = valid_lens[b];

    if (q0 >= vl) {  // whole block invalid: ctx rows = LN(0) = ln1_b
        if (t < 128) {
            int qt = t >> 6, d = t & 63;
            out[(b * NN + q0 + qt) * FF + d] = ln1_b[d];
        }
        return;
    }

    int j = t;
    float aq0 = g_Aq[(b * NN + q0) * H1 + j];
    float aq1 = g_Aq[(b * NN + q0 + 1) * H1 + j];
    float w5[5];
    #pragma unroll
    for (int c = 0; c < 5; c++) w5[c] = Wa1[(2 * FF + c) * H1 + j];
    float ba3v = ba3[0];

    int jq = t & 15;       // j-quad within sub-sweep
    int pg = t >> 4;       // pair-octet group (0..15)
    const float4* W4  = reinterpret_cast<const float4*>(Wa2);   // rows of 64 float4
    const float4* B24 = reinterpret_cast<const float4*>(ba2);
    const float4* W34 = reinterpret_cast<const float4*>(Wa3);
    const float* g1p = g1T + pg * 8;

    float ctxacc = 0.0f;   // t<128 owns (qt=t>>6, d=t&63)

    for (int tile = 0; tile < NTILE; tile++) {
        int kbase = tile * KB;

        // ---- extras for 128 pairs ----
        if (t < P) {
            int qt = t >> 6, kk = t & 63;
            int q = q0 + qt, k = kbase + kk;
            float e0 = qs_s[(b * NN + q) * 2]     - ks_s[(b * NN + k) * 2];
            float e1 = qs_s[(b * NN + q) * 2 + 1] - ks_s[(b * NN + k) * 2 + 1];
            float d2 = e0 * e0 + e1 * e1;
            float e4 = qs_t[b * NN + q] - ks_t[b * NN + k];
            ex4s[t] = make_float4(e0, e1, sqrtf(d2), d2);
            exts[t] = e4;
        }
        __syncthreads();

        // ---- phase A: g1 = gelu(layer1), transposed [i=j][p], STS.128 ----
        #pragma unroll 4
        for (int kk4 = 0; kk4 < 16; kk4++) {
            float a[4];
            #pragma unroll
            for (int r = 0; r < 4; r++)
                a[r] = g_Ak[(b * NN + kbase + kk4 * 4 + r) * H1 + j];
            #pragma unroll
            for (int qt = 0; qt < 2; qt++) {
                float aqv = qt ? aq1 : aq0;
                float4 o;
                float vv[4];
                #pragma unroll
                for (int r = 0; r < 4; r++) {
                    int p = qt * KB + kk4 * 4 + r;
                    float4 e = ex4s[p];
                    float et = exts[p];
                    float x = aqv + a[r];
                    x = fmaf(e.x, w5[0], x);
                    x = fmaf(e.y, w5[1], x);
                    x = fmaf(e.z, w5[2], x);
                    x = fmaf(e.w, w5[3], x);
                    x = fmaf(et,  w5[4], x);
                    vv[r] = gelu_t(x);
                }
                o.x = vv[0]; o.y = vv[1]; o.z = vv[2]; o.w = vv[3];
                *reinterpret_cast<float4*>(&g1T[j * PL + qt * KB + kk4 * 4]) = o;
            }
        }
        __syncthreads();

        // ---- GEMM: 4 j-sub-sweeps, each thread = 8 pairs x 4 j ----
        float part[8];
        #pragma unroll
        for (int r = 0; r < 8; r++) part[r] = 0.0f;

        #pragma unroll 1
        for (int s = 0; s < 4; s++) {
            int wbase = s * 16 + jq;
            float4 ba2v = B24[wbase];
            float4 wa3v = W34[wbase];

            unsigned long long acc[16];
            #pragma unroll
            for (int r = 0; r < 16; r++) acc[r] = 0ULL;

            float4 wbuf[4];
            #pragma unroll
            for (int r = 0; r < 4; r++) wbuf[r] = W4[r * 64 + wbase];

            #pragma unroll 1
            for (int ib = 0; ib < 64; ib++) {
                #pragma unroll
                for (int u = 0; u < 4; u++) {
                    int i = ib * 4 + u;
                    float4 wcur = wbuf[u];
                    if (ib < 63) wbuf[u] = W4[(i + 4) * 64 + wbase];
                    ulonglong2 ga = *reinterpret_cast<const ulonglong2*>(g1p + i * PL);
                    ulonglong2 gb = *reinterpret_cast<const ulonglong2*>(g1p + i * PL + 4);
                    unsigned long long wd0, wd1, wd2, wd3;
                    asm("mov.b64 %0, {%1, %1};" : "=l"(wd0) : "f"(wcur.x));
                    asm("mov.b64 %0, {%1, %1};" : "=l"(wd1) : "f"(wcur.y));
                    asm("mov.b64 %0, {%1, %1};" : "=l"(wd2) : "f"(wcur.z));
                    asm("mov.b64 %0, {%1, %1};" : "=l"(wd3) : "f"(wcur.w));
                    asm("fma.rn.f32x2 %0, %1, %2, %0;" : "+l"(acc[0])  : "l"(ga.x), "l"(wd0));
                    asm("fma.rn.f32x2 %0, %1, %2, %0;" : "+l"(acc[1])  : "l"(ga.y), "l"(wd0));
                    asm("fma.rn.f32x2 %0, %1, %2, %0;" : "+l"(acc[2])  : "l"(gb.x), "l"(wd0));
                    asm("fma.rn.f32x2 %0, %1, %2, %0;" : "+l"(acc[3])  : "l"(gb.y), "l"(wd0));
                    asm("fma.rn.f32x2 %0, %1, %2, %0;" : "+l"(acc[4])  : "l"(ga.x), "l"(wd1));
                    asm("fma.rn.f32x2 %0, %1, %2, %0;" : "+l"(acc[5])  : "l"(ga.y), "l"(wd1));
                    asm("fma.rn.f32x2 %0, %1, %2, %0;" : "+l"(acc[6])  : "l"(gb.x), "l"(wd1));
                    asm("fma.rn.f32x2 %0, %1, %2, %0;" : "+l"(acc[7])  : "l"(gb.y), "l"(wd1));
                    asm("fma.rn.f32x2 %0, %1, %2, %0;" : "+l"(acc[8])  : "l"(ga.x), "l"(wd2));
                    asm("fma.rn.f32x2 %0, %1, %2, %0;" : "+l"(acc[9])  : "l"(ga.y), "l"(wd2));
                    asm("fma.rn.f32x2 %0, %1, %2, %0;" : "+l"(acc[10]) : "l"(gb.x), "l"(wd2));
                    asm("fma.rn.f32x2 %0, %1, %2, %0;" : "+l"(acc[11]) : "l"(gb.y), "l"(wd2));
                    asm("fma.rn.f32x2 %0, %1, %2, %0;" : "+l"(acc[12]) : "l"(ga.x), "l"(wd3));
                    asm("fma.rn.f32x2 %0, %1, %2, %0;" : "+l"(acc[13]) : "l"(ga.y), "l"(wd3));
                    asm("fma.rn.f32x2 %0, %1, %2, %0;" : "+l"(acc[14]) : "l"(gb.x), "l"(wd3));
                    asm("fma.rn.f32x2 %0, %1, %2, %0;" : "+l"(acc[15]) : "l"(gb.y), "l"(wd3));
                }
            }

            // epilogue: bias, gelu, *Wa3, accumulate per-pair partials
            float bj[4] = {ba2v.x, ba2v.y, ba2v.z, ba2v.w};
            float wj[4] = {wa3v.x, wa3v.y, wa3v.z, wa3v.w};
            #pragma unroll
            for (int jj = 0; jj < 4; jj++) {
                #pragma unroll
                for (int pp2 = 0; pp2 < 4; pp2++) {
                    float lo, hi;
                    asm("mov.b64 {%0, %1}, %2;" : "=f"(lo), "=f"(hi) : "l"(acc[jj * 4 + pp2]));
                    part[pp2 * 2]     += gelu_t(lo + bj[jj]) * wj[jj];
                    part[pp2 * 2 + 1] += gelu_t(hi + bj[jj]) * wj[jj];
                }
            }
        }

        // ---- reduce over jq (16 lanes), mask, write attn ----
        #pragma unroll
        for (int r = 0; r < 8; r++) {
            float v = part[r];
            v += __shfl_xor_sync(0xffffffffu, v, 1);
            v += __shfl_xor_sync(0xffffffffu, v, 2);
            v += __shfl_xor_sync(0xffffffffu, v, 4);
            v += __shfl_xor_sync(0xffffffffu, v, 8);
            part[r] = v;
        }
        if (jq == 0) {
            #pragma unroll
            for (int r = 0; r < 8; r++) {
                int p = pg * 8 + r;
                int qt = p >> 6;
                bool ok = ((q0 + qt) < vl) && (exts[p] > 0.0f);
                attn_s[p] = ok ? (ba3v + part[r]) : 0.0f;
            }
        }
        __syncthreads();

        // ---- ctx accumulation ----
        if (t < 128) {
            int qt = t >> 6, d = t & 63;
            const float* vp = g_vproj + (b * NN + kbase) * FF + d;
            #pragma unroll 8
            for (int kk = 0; kk < KB; kk++)
                ctxacc = fmaf(attn_s[qt * KB + kk], vp[kk * FF], ctxacc);
        }
        __syncthreads();
    }

    // ---- LayerNorm over d=64 per q-row ----
    float x = ctxacc;
    float s = warp_sum(x);
    if (lane == 0) lnred[wrp] = s;
    __syncthreads();
    int g2 = (t >> 6) & 3;
    float mu = (lnred[g2 * 2] + lnred[g2 * 2 + 1]) * (1.0f / 64.0f);
    float y = x - mu;
    float s2 = warp_sum(y * y);
    if (lane == 0) lnred[8 + wrp] = s2;
    __syncthreads();
    float var = (lnred[8 + g2 * 2] + lnred[8 + g2 * 2 + 1]) * (1.0f / 64.0f);
    if (t < 128) {
        int qt = t >> 6, d = t & 63;
        float o = y * rsqrtf(var + 1e-6f) * ln1_s[d] + ln1_b[d];
        out[(b * NN + q0 + qt) * FF + d] = o;
    }
}

// ---------------- K3: gate MLP + masked max-pool partials ----------------
__global__ void k_gate(const float* __restrict__ ctx, const int* __restrict__ valid_lens,
                       const float* __restrict__ Wg1, const float* __restrict__ bg1,
                       const float* __restrict__ Wg2, const float* __restrict__ bg2)
{
    __shared__ float ctx_s[32 * FF];
    __shared__ float hs[H1];
    __shared__ float gsum[4 * FF];
    int t = threadIdx.x;
    int b = blockIdx.x >> 4;
    int qg = blockIdx.x & 15;
    int qbase = qg * 32;
    int vl = valid_lens[b];
    #pragma unroll
    for (int u = 0; u < 8; u++)
        ctx_s[t + 256 * u] = ctx[(b * NN + qbase) * FF + t + 256 * u];
    __syncthreads();

    float lmax = -3.4e38f;
    for (int q = 0; q < 32; q++) {
        float a = bg1[t];
        #pragma unroll 8
        for (int f = 0; f < FF; f++) a = fmaf(ctx_s[q * FF + f], Wg1[f * H1 + t], a);
        hs[t] = gelu_t(a);
        __syncthreads();
        int d = t & 63, part = t >> 6;
        float s = 0.0f;
        #pragma unroll 8
        for (int jj = 0; jj < 64; jj++)
            s = fmaf(hs[part * 64 + jj], Wg2[(part * 64 + jj) * FF + d], s);
        gsum[part * FF + d] = s;
        __syncthreads();
        if (t < FF) {
            float g = bg2[t] + gsum[t] + gsum[FF + t] + gsum[2 * FF + t] + gsum[3 * FF + t];
            float gp = g * ctx_s[q * FF + t];
            float m = ((qbase + q) < vl) ? gp : -3.4e38f;
            lmax = fmaxf(lmax, m);
        }
        __syncthreads();
    }
    if (t < FF) g_gpart[(b * 16 + qg) * FF + t] = lmax;
}

// ---------------- K4: final max + LN -> vnode ----------------
__global__ void k_vnode(float* __restrict__ out,
                        const float* __restrict__ ln2_s, const float* __restrict__ ln2_b) {
    __shared__ float r4[4];
    int b = blockIdx.x, d = threadIdx.x;
    float m = -3.4e38f;
    #pragma unroll
    for (int g = 0; g < 16; g++) m = fmaxf(m, g_gpart[(b * 16 + g) * FF + d]);
    float s = warp_sum(m);
    if ((d & 31) == 0) r4[d >> 5] = s;
    __syncthreads();
    float mu = (r4[0] + r4[1]) * (1.0f / 64.0f);
    float y = m - mu;
    float s2 = warp_sum(y * y);
    if ((d & 31) == 0) r4[2 + (d >> 5)] = s2;
    __syncthreads();
    float var = (r4[2] + r4[3]) * (1.0f / 64.0f);
    out[BB * NN * FF + b * FF + d] = y * rsqrtf(var + 1e-6f) * ln2_s[d] + ln2_b[d];
}

// ---------------- launch ----------------
extern "C" void kernel_launch(void* const* d_in, const int* in_sizes, int n_in,
                              void* d_out, int out_size) {
    (void)in_sizes; (void)n_in; (void)out_size;
    const float* qs    = (const float*)d_in[0];
    const float* ks    = (const float*)d_in[1];
    const float* vs    = (const float*)d_in[2];
    const float* qs_s  = (const float*)d_in[3];
    const float* ks_s  = (const float*)d_in[4];
    const float* qs_t  = (const float*)d_in[5];
    const float* ks_t  = (const float*)d_in[6];
    const int*   vlen  = (const int*)  d_in[7];
    const float* Wv    = (const float*)d_in[8];
    const float* bv    = (const float*)d_in[9];
    const float* Wa1   = (const float*)d_in[10];
    const float* ba1   = (const float*)d_in[11];
    const float* Wa2   = (const float*)d_in[12];
    const float* ba2   = (const float*)d_in[13];
    const float* Wa3   = (const float*)d_in[14];
    const float* ba3   = (const float*)d_in[15];
    const float* Wg1   = (const float*)d_in[16];
    const float* bg1   = (const float*)d_in[17];
    const float* Wg2   = (const float*)d_in[18];
    const float* bg2   = (const float*)d_in[19];
    const float* ln1_s = (const float*)d_in[20];
    const float* ln1_b = (const float*)d_in[21];
    const float* ln2_s = (const float*)d_in[22];
    const float* ln2_b = (const float*)d_in[23];
    float* out = (float*)d_out;

    static int smem_set = 0;
    const int smem_bytes = SM_FLOATS * 4;   // ~138.3 KB
    if (!smem_set) {
        cudaFuncSetAttribute(k_main, cudaFuncAttributeMaxDynamicSharedMemorySize, smem_bytes);
        smem_set = 1;
    }

    k_pre  <<<144, 256>>>(qs, ks, vs, Wa1, ba1, Wv, bv);
    k_main <<<BB * (NN / QT), 256, smem_bytes>>>(qs_s, ks_s, qs_t, ks_t, vlen,
                                                 Wa1, Wa2, ba2, Wa3, ba3, ln1_s, ln1_b, out);
    k_gate <<<32, 256>>>(out, vlen, Wg1, bg1, Wg2, bg2);
    k_vnode<<<BB, 64>>>(out, ln2_s, ln2_b);
}